// round 1
// baseline (speedup 1.0000x reference)
#include <cuda_runtime.h>

// ConsistencyLoss: B=8192, E=16, H=1024
// loss = mean over {(i,j): cos_sim(e_i,e_j) > 0.8, i != j} of KL(P_j || P_i)
//
// Fused plan:
//   k1: L2-normalize embeddings -> g_embn (fp32)
//   k2: per-row log_softmax stats: g_L, g_P, g_ne (neg entropy)
//   k3: tiled Gram pass over UPPER-TRIANGULAR 128x128 tiles; per masked pair
//       accumulate kl[i,j] (+ kl[j,i] for off-diag tiles) and count
//   k4: finalize scalar
//
// No sim/kl matrices materialized. No allocations; scratch = __device__ globals.

#define BDIM 8192
#define HDIM 1024
#define EDIM 16
#define TILE 128
#define NT   (BDIM / TILE)            // 64
#define NBLK (NT * (NT + 1) / 2)      // 2080
#define BK   16
#define SIM_THR 0.8f

__device__ float  g_embn[BDIM * HDIM];     // normalized embeddings (32 MB)
__device__ float  g_L[BDIM * EDIM];        // log_softmax
__device__ float  g_P[BDIM * EDIM];        // softmax
__device__ float  g_ne[BDIM];              // sum_k P*L  (neg entropy)
__device__ double g_sum;
__device__ unsigned long long g_cnt;

__global__ void init_kernel() {
    g_sum = 0.0;
    g_cnt = 0ull;
}

// One block per row; 256 threads x float4 = 1024 elems.
__global__ void normalize_kernel(const float* __restrict__ emb) {
    int row = blockIdx.x;
    int t = threadIdx.x;
    float4 v = reinterpret_cast<const float4*>(emb + (size_t)row * HDIM)[t];
    float ss = v.x * v.x + v.y * v.y + v.z * v.z + v.w * v.w;
    #pragma unroll
    for (int o = 16; o > 0; o >>= 1) ss += __shfl_down_sync(0xffffffffu, ss, o);
    __shared__ float red[8];
    int lane = t & 31, w = t >> 5;
    if (lane == 0) red[w] = ss;
    __syncthreads();
    if (t < 32) {
        float s = (t < 8) ? red[t] : 0.f;
        #pragma unroll
        for (int o = 4; o > 0; o >>= 1) s += __shfl_down_sync(0xffffffffu, s, o);
        if (t == 0) red[0] = s;
    }
    __syncthreads();
    float inv = 1.0f / sqrtf(red[0]);
    float4 o4 = make_float4(v.x * inv, v.y * inv, v.z * inv, v.w * inv);
    reinterpret_cast<float4*>(g_embn + (size_t)row * HDIM)[t] = o4;
}

// One thread per row (E=16).
__global__ void routing_kernel(const float* __restrict__ rp) {
    int row = blockIdx.x * blockDim.x + threadIdx.x;
    if (row >= BDIM) return;
    float x[EDIM];
    float m = -1e30f;
    #pragma unroll
    for (int e = 0; e < EDIM; e++) { x[e] = rp[row * EDIM + e]; m = fmaxf(m, x[e]); }
    float s = 0.f;
    #pragma unroll
    for (int e = 0; e < EDIM; e++) s += expf(x[e] - m);
    float lse = m + logf(s);
    float ne = 0.f;
    #pragma unroll
    for (int e = 0; e < EDIM; e++) {
        float L = x[e] - lse;
        float P = expf(L);
        g_L[row * EDIM + e] = L;
        g_P[row * EDIM + e] = P;
        ne = fmaf(P, L, ne);
    }
    g_ne[row] = ne;
}

// Main fused kernel: one block = one 128x128 tile (ti <= tj), 256 threads,
// 8x8 outputs per thread. Shared buffer is reused between GEMM stage and
// the L/P/ne staging for the epilogue.
__global__ __launch_bounds__(256, 1) void main_kernel() {
    __shared__ float smem[8448];           // max(2*BK*TILE, 4*2048 + 256) floats
    __shared__ float rs[8];
    __shared__ unsigned int rc[8];

    // linear block id -> (ti, tj) with tj >= ti
    int ti = 0, rem = blockIdx.x;
    while (rem >= NT - ti) { rem -= NT - ti; ti++; }
    int tj = ti + rem;

    int tid = threadIdx.x;
    int tx = tid & 15;      // n dim
    int ty = tid >> 4;      // m dim

    float* As = smem;                 // [BK][TILE]
    float* Bs = smem + BK * TILE;     // [BK][TILE]

    float acc[8][8];
    #pragma unroll
    for (int m = 0; m < 8; m++)
        #pragma unroll
        for (int n = 0; n < 8; n++) acc[m][n] = 0.f;

    const float* Abase = g_embn + (size_t)(ti * TILE) * HDIM;
    const float* Bbase = g_embn + (size_t)(tj * TILE) * HDIM;

    for (int k0 = 0; k0 < HDIM; k0 += BK) {
        #pragma unroll
        for (int r = 0; r < 2; r++) {
            int slot = tid + r * 256;        // 0..511
            int row = slot >> 2;             // 0..127
            int q = slot & 3;                // float4 quad within BK=16
            float4 va = *reinterpret_cast<const float4*>(Abase + row * HDIM + k0 + q * 4);
            float4 vb = *reinterpret_cast<const float4*>(Bbase + row * HDIM + k0 + q * 4);
            As[(q * 4 + 0) * TILE + row] = va.x;
            As[(q * 4 + 1) * TILE + row] = va.y;
            As[(q * 4 + 2) * TILE + row] = va.z;
            As[(q * 4 + 3) * TILE + row] = va.w;
            Bs[(q * 4 + 0) * TILE + row] = vb.x;
            Bs[(q * 4 + 1) * TILE + row] = vb.y;
            Bs[(q * 4 + 2) * TILE + row] = vb.z;
            Bs[(q * 4 + 3) * TILE + row] = vb.w;
        }
        __syncthreads();
        #pragma unroll
        for (int k = 0; k < BK; k++) {
            float4 a0 = *reinterpret_cast<const float4*>(&As[k * TILE + ty * 8]);
            float4 a1 = *reinterpret_cast<const float4*>(&As[k * TILE + ty * 8 + 4]);
            float4 b0 = *reinterpret_cast<const float4*>(&Bs[k * TILE + tx * 8]);
            float4 b1 = *reinterpret_cast<const float4*>(&Bs[k * TILE + tx * 8 + 4]);
            float av[8] = {a0.x, a0.y, a0.z, a0.w, a1.x, a1.y, a1.z, a1.w};
            float bv[8] = {b0.x, b0.y, b0.z, b0.w, b1.x, b1.y, b1.z, b1.w};
            #pragma unroll
            for (int m = 0; m < 8; m++)
                #pragma unroll
                for (int n = 0; n < 8; n++)
                    acc[m][n] = fmaf(av[m], bv[n], acc[m][n]);
        }
        __syncthreads();
    }

    // ---- epilogue: stage L/P/ne for both row-block and col-block ----
    float* Lr = smem;                  // [128][16] row-block log_softmax
    float* Pr = smem + 2048;           // [128][16] row-block softmax
    float* Lc = smem + 4096;           // [128][16] col-block log_softmax
    float* Pc = smem + 6144;           // [128][16] col-block softmax
    float* nr = smem + 8192;           // [128] row-block neg-entropy
    float* nc = smem + 8320;           // [128] col-block neg-entropy

    #pragma unroll
    for (int r = 0; r < 2; r++) {
        int slot = tid + r * 256;
        int row = slot >> 2;
        int q = (slot & 3) * 4;
        *reinterpret_cast<float4*>(&Lr[row * 16 + q]) =
            *reinterpret_cast<const float4*>(&g_L[(ti * TILE + row) * EDIM + q]);
        *reinterpret_cast<float4*>(&Pr[row * 16 + q]) =
            *reinterpret_cast<const float4*>(&g_P[(ti * TILE + row) * EDIM + q]);
        *reinterpret_cast<float4*>(&Lc[row * 16 + q]) =
            *reinterpret_cast<const float4*>(&g_L[(tj * TILE + row) * EDIM + q]);
        *reinterpret_cast<float4*>(&Pc[row * 16 + q]) =
            *reinterpret_cast<const float4*>(&g_P[(tj * TILE + row) * EDIM + q]);
    }
    if (tid < 128) {
        nr[tid] = g_ne[ti * TILE + tid];
        nc[tid] = g_ne[tj * TILE + tid];
    }
    __syncthreads();

    float lsum = 0.f;
    unsigned int lcnt = 0;
    bool diag = (ti == tj);
    #pragma unroll
    for (int m = 0; m < 8; m++) {
        int i = ty * 8 + m;
        #pragma unroll
        for (int n = 0; n < 8; n++) {
            int j = tx * 8 + n;
            float s = acc[m][n];
            if (s > SIM_THR && (!diag || i != j)) {
                // kl[i,j] = ne[j] - dot(L_i, P_j)
                float d1 = 0.f;
                #pragma unroll
                for (int e = 0; e < EDIM; e++)
                    d1 = fmaf(Lr[i * 16 + e], Pc[j * 16 + e], d1);
                float kl_ij = nc[j] - d1;
                if (diag) {
                    lsum += kl_ij;
                    lcnt += 1u;
                } else {
                    // kl[j,i] = ne[i] - dot(L_j, P_i)
                    float d2 = 0.f;
                    #pragma unroll
                    for (int e = 0; e < EDIM; e++)
                        d2 = fmaf(Lc[j * 16 + e], Pr[i * 16 + e], d2);
                    lsum += kl_ij + (nr[i] - d2);
                    lcnt += 2u;
                }
            }
        }
    }

    // block reduce + one atomic per block
    #pragma unroll
    for (int o = 16; o > 0; o >>= 1) {
        lsum += __shfl_down_sync(0xffffffffu, lsum, o);
        lcnt += __shfl_down_sync(0xffffffffu, lcnt, o);
    }
    int lane = tid & 31, w = tid >> 5;
    if (lane == 0) { rs[w] = lsum; rc[w] = lcnt; }
    __syncthreads();
    if (tid == 0) {
        float ts = 0.f;
        unsigned int tc = 0;
        #pragma unroll
        for (int q = 0; q < 8; q++) { ts += rs[q]; tc += rc[q]; }
        if (tc > 0) {
            atomicAdd(&g_sum, (double)ts);
            atomicAdd(&g_cnt, (unsigned long long)tc);
        }
    }
}

__global__ void finalize_kernel(float* __restrict__ out) {
    unsigned long long c = g_cnt;
    out[0] = (c > 0) ? (float)(g_sum / (double)c) : 0.0f;   // WEIGHT = 1.0
}

extern "C" void kernel_launch(void* const* d_in, const int* in_sizes, int n_in,
                              void* d_out, int out_size) {
    // metadata order: routing_probs [B,E], input_embeddings [B,H]; guard anyway.
    const float* rp;
    const float* emb;
    if (in_sizes[0] == BDIM * EDIM) {
        rp = (const float*)d_in[0];
        emb = (const float*)d_in[1];
    } else {
        rp = (const float*)d_in[1];
        emb = (const float*)d_in[0];
    }
    float* out = (float*)d_out;

    init_kernel<<<1, 1>>>();
    normalize_kernel<<<BDIM, 256>>>(emb);
    routing_kernel<<<BDIM / 256, 256>>>(rp);
    main_kernel<<<NBLK, 256>>>();
    finalize_kernel<<<1, 1>>>(out);
}

// round 3
// speedup vs baseline: 3.3492x; 3.3492x over previous
#include <cuda_runtime.h>
#include <cuda_bf16.h>
#include <cstdint>

// ConsistencyLoss: B=8192, E=16, H=1024
// Round 3: dual-path tensor-core Gram GEMM over upper-triangular 128x128 tiles
// with fused masked-KL epilogue.
//   Path A (sm_103a pass only): tcgen05 SS bf16 MMA, TMEM accumulator.
//   Path B (any target):        mma.sync m16n8k16 bf16 + ldmatrix + cp.async.
// The compute_103 (non-'a') gencode pass compiles Path B only, so ptxas never
// sees 'a'-gated tcgen05.ld/wait/fence instructions in that pass.

#if defined(__CUDA_ARCH__) && (defined(__CUDA_ARCH_FEAT_SM103_ALL) || defined(__CUDA_ARCH_FEAT_SM100_ALL))
#define HAS_TCGEN05 1
#else
#define HAS_TCGEN05 0
#endif

#define BDIM 8192
#define HDIM 1024
#define EDIM 16
#define TILE 128
#define NT   (BDIM / TILE)            // 64
#define NBLK (NT * (NT + 1) / 2)      // 2080
#define SIM_THR 0.8f

#define SM_TOTAL 66560

__device__ __nv_bfloat16 g_embn[BDIM * HDIM];   // normalized embeddings, bf16 (16 MB)
__device__ float  g_L[BDIM * EDIM];
__device__ float  g_P[BDIM * EDIM];
__device__ float  g_ne[BDIM];
__device__ double g_sum;
__device__ unsigned long long g_cnt;

// ---------------- common helpers ----------------
__device__ __forceinline__ uint32_t smem_u32(const void* p) {
    uint32_t a;
    asm("{ .reg .u64 t; cvta.to.shared.u64 t, %1; cvt.u32.u64 %0, t; }" : "=r"(a) : "l"(p));
    return a;
}

// ---------------- prep kernels ----------------
__global__ void init_kernel() { g_sum = 0.0; g_cnt = 0ull; }

__global__ void normalize_kernel(const float* __restrict__ emb) {
    int row = blockIdx.x;
    int t = threadIdx.x;
    float4 v = reinterpret_cast<const float4*>(emb + (size_t)row * HDIM)[t];
    float ss = v.x * v.x + v.y * v.y + v.z * v.z + v.w * v.w;
    #pragma unroll
    for (int o = 16; o > 0; o >>= 1) ss += __shfl_down_sync(0xffffffffu, ss, o);
    __shared__ float red[8];
    int lane = t & 31, w = t >> 5;
    if (lane == 0) red[w] = ss;
    __syncthreads();
    if (t < 32) {
        float s = (t < 8) ? red[t] : 0.f;
        #pragma unroll
        for (int o = 4; o > 0; o >>= 1) s += __shfl_down_sync(0xffffffffu, s, o);
        if (t == 0) red[0] = s;
    }
    __syncthreads();
    float inv = rsqrtf(red[0]);
    __nv_bfloat162 h0 = __floats2bfloat162_rn(v.x * inv, v.y * inv);
    __nv_bfloat162 h1 = __floats2bfloat162_rn(v.z * inv, v.w * inv);
    uint2 o2;
    *reinterpret_cast<__nv_bfloat162*>(&o2.x) = h0;
    *reinterpret_cast<__nv_bfloat162*>(&o2.y) = h1;
    reinterpret_cast<uint2*>(g_embn + (size_t)row * HDIM)[t] = o2;
}

__global__ void routing_kernel(const float* __restrict__ rp) {
    int row = blockIdx.x * blockDim.x + threadIdx.x;
    if (row >= BDIM) return;
    float x[EDIM];
    float m = -1e30f;
    #pragma unroll
    for (int e = 0; e < EDIM; e++) { x[e] = rp[row * EDIM + e]; m = fmaxf(m, x[e]); }
    float s = 0.f;
    #pragma unroll
    for (int e = 0; e < EDIM; e++) s += expf(x[e] - m);
    float lse = m + logf(s);
    float ne = 0.f;
    #pragma unroll
    for (int e = 0; e < EDIM; e++) {
        float L = x[e] - lse;
        float P = expf(L);
        g_L[row * EDIM + e] = L;
        g_P[row * EDIM + e] = P;
        ne = fmaf(P, L, ne);
    }
    g_ne[row] = ne;
}

#if HAS_TCGEN05
// ================= Path A: tcgen05 =================
#define MMA_IDESC 0x8200490u   // f32 acc, bf16 x bf16, M=128, N=128
#define BKC  64                // bf16 per chunk (128B row, SW128 atom)
#define NCHUNK (HDIM / BKC)    // 16

#define SM_TMEM  0
#define SM_MBAR0 16
#define SM_MBAR1 24
#define SM_RS    64
#define SM_RC    96
#define SM_A0    1024
#define SM_B0    (SM_A0 + 16384)
#define SM_A1    (SM_B0 + 16384)
#define SM_B1    (SM_A1 + 16384)
#define SM_LC    1024
#define SM_PC    (1024 + 8192)
#define SM_NC    (1024 + 16384)

__device__ __forceinline__ uint32_t elect_one() {
    uint32_t pred;
    asm volatile("{\n\t.reg .pred p;\n\telect.sync _|p, 0xFFFFFFFF;\n\t"
                 "selp.b32 %0, 1, 0, p;\n\t}" : "=r"(pred));
    return pred;
}
#define SW128(off) ((off) ^ (((off) >> 3) & 0x70))
#define MBAR_INIT(addr, cnt) \
    asm volatile("mbarrier.init.shared.b64 [%0], %1;" :: "r"(addr), "r"(cnt) : "memory")
#define MBAR_INVAL(addr) \
    asm volatile("mbarrier.inval.shared.b64 [%0];" :: "r"(addr) : "memory")
#define MBAR_WAIT(addr, parity) do {                                           \
    uint32_t _m = (addr), _p = (parity), _done;                                \
    asm volatile("{\n\t.reg .pred p;\n\t"                                      \
        "mbarrier.try_wait.parity.acquire.cta.shared::cta.b64 p, [%1], %2;\n\t"\
        "selp.b32 %0, 1, 0, p;\n\t}" : "=r"(_done) : "r"(_m), "r"(_p) : "memory"); \
    if (!_done) {                                                              \
        asm volatile("{\n\t.reg .pred P1;\n\t"                                 \
            "WL_%=:\n\t"                                                       \
            "mbarrier.try_wait.parity.acquire.cta.shared::cta.b64 P1, [%0], %1, 0x989680;\n\t" \
            "@P1 bra.uni WD_%=;\n\t"                                           \
            "bra.uni WL_%=;\n\t"                                               \
            "WD_%=:\n\t}" :: "r"(_m), "r"(_p) : "memory");                     \
    }                                                                          \
} while (0)
#define TC_ALLOC(sa, cols) \
    asm volatile("tcgen05.alloc.cta_group::1.sync.aligned.shared::cta.b32 [%0], %1;" \
                 :: "r"(sa), "r"((uint32_t)(cols)) : "memory")
#define TC_DEALLOC(tm, cols) \
    asm volatile("tcgen05.dealloc.cta_group::1.sync.aligned.b32 %0, %1;" \
                 :: "r"(tm), "r"((uint32_t)(cols)))
#define TC_RELINQ() \
    asm volatile("tcgen05.relinquish_alloc_permit.cta_group::1.sync.aligned;")
#define TC_COMMIT(mbar) \
    asm volatile("tcgen05.commit.cta_group::1.mbarrier::arrive::one.shared::cluster.b64 [%0];" \
                 :: "r"(mbar) : "memory")
#define TC_FENCE_AFTER() asm volatile("tcgen05.fence::after_thread_sync;" ::: "memory")
#define TC_FENCE_BEFORE() asm volatile("tcgen05.fence::before_thread_sync;" ::: "memory")
#define TC_WAIT_LD() asm volatile("tcgen05.wait::ld.sync.aligned;" ::: "memory")
#define FENCE_ASYNC() asm volatile("fence.proxy.async.shared::cta;" ::: "memory")
#define STS128A(a, x, y, z, w) \
    asm volatile("st.shared.v4.b32 [%0], {%1, %2, %3, %4};" \
                 :: "r"(a), "r"(x), "r"(y), "r"(z), "r"(w) : "memory")

static constexpr uint64_t DESC_BASE =
    (uint64_t(2) << 61) | (uint64_t(1) << 46) | (uint64_t(64) << 32) | (uint64_t(1) << 16);
#define MK_DESC(addr) (DESC_BASE | ((uint64_t)((addr) >> 4) & 0x3FFF))

__device__ __forceinline__ void mma_f16_ss(uint32_t d, uint64_t a, uint64_t b,
                                           uint32_t idesc, bool acc) {
    uint32_t en = acc ? 1u : 0u;
    asm volatile(
        "{\n\t.reg .pred p;\n\t"
        "setp.ne.u32 p, %5, 0;\n\t"
        "tcgen05.mma.cta_group::1.kind::f16 [%0], %1, %2, %3, {%4, %4, %4, %4}, p;\n\t"
        "}"
        :: "r"(d), "l"(a), "l"(b), "r"(idesc), "r"(0u), "r"(en) : "memory");
}

#define LDTM_X32(r, addr) \
    asm volatile( \
        "tcgen05.ld.sync.aligned.32x32b.x32.b32 " \
        "{%0, %1, %2, %3, %4, %5, %6, %7, " \
        " %8, %9, %10, %11, %12, %13, %14, %15, " \
        " %16, %17, %18, %19, %20, %21, %22, %23, " \
        " %24, %25, %26, %27, %28, %29, %30, %31}, [%32];" \
        : "=r"((r)[0]),  "=r"((r)[1]),  "=r"((r)[2]),  "=r"((r)[3]), \
          "=r"((r)[4]),  "=r"((r)[5]),  "=r"((r)[6]),  "=r"((r)[7]), \
          "=r"((r)[8]),  "=r"((r)[9]),  "=r"((r)[10]), "=r"((r)[11]), \
          "=r"((r)[12]), "=r"((r)[13]), "=r"((r)[14]), "=r"((r)[15]), \
          "=r"((r)[16]), "=r"((r)[17]), "=r"((r)[18]), "=r"((r)[19]), \
          "=r"((r)[20]), "=r"((r)[21]), "=r"((r)[22]), "=r"((r)[23]), \
          "=r"((r)[24]), "=r"((r)[25]), "=r"((r)[26]), "=r"((r)[27]), \
          "=r"((r)[28]), "=r"((r)[29]), "=r"((r)[30]), "=r"((r)[31]) \
        : "r"(addr))
#endif  // HAS_TCGEN05

// ---------------- main fused kernel ----------------
__global__ __launch_bounds__(256) void main_kernel() {
    extern __shared__ char smem[];
    uint32_t sb = smem_u32(smem);
    int tid = threadIdx.x;
    int wid = tid >> 5, lane = tid & 31;

    // block -> (ti, tj), tj >= ti
    int ti = 0, rem = blockIdx.x;
    while (rem >= NT - ti) { rem -= NT - ti; ti++; }
    int tj = ti + rem;
    bool diag = (ti == tj);

    float sumv = 0.f;
    unsigned int cntv = 0;

#if HAS_TCGEN05
    // ======== Path A: tcgen05 ========
    if (wid == 0) TC_ALLOC(sb + SM_TMEM, 128);
    if (tid == 0) { MBAR_INIT(sb + SM_MBAR0, 1); MBAR_INIT(sb + SM_MBAR1, 1); }
    __syncthreads();
    uint32_t tmem;
    asm volatile("ld.shared.b32 %0, [%1];" : "=r"(tmem) : "r"(sb + SM_TMEM));
    if (wid == 0) TC_RELINQ();

    int row = tid & 127;
    const __nv_bfloat16* src =
        g_embn + (size_t)(((tid < 128) ? ti : tj) * TILE + row) * HDIM;
    uint32_t db0 = sb + ((tid < 128) ? SM_A0 : SM_B0);
    uint32_t db1 = sb + ((tid < 128) ? SM_A1 : SM_B1);

    int ph0 = 0, ph1 = 0;
    for (int kc = 0; kc < NCHUNK; kc++) {
        int buf = kc & 1;
        if (kc >= 2) {
            if (buf == 0) { MBAR_WAIT(sb + SM_MBAR0, ph0); ph0 ^= 1; }
            else          { MBAR_WAIT(sb + SM_MBAR1, ph1); ph1 ^= 1; }
        }
        const uint4* s4 = reinterpret_cast<const uint4*>(src + kc * BKC);
        uint32_t db = buf ? db1 : db0;
        #pragma unroll
        for (int q = 0; q < 8; q++) {
            uint4 v = s4[q];
            uint32_t off = row * 128 + q * 16;
            STS128A(db + SW128(off), v.x, v.y, v.z, v.w);
        }
        FENCE_ASYNC();
        __syncthreads();
        if (wid == 0 && elect_one()) {
            uint64_t ad = MK_DESC(sb + (buf ? SM_A1 : SM_A0));
            uint64_t bd = MK_DESC(sb + (buf ? SM_B1 : SM_B0));
            #pragma unroll
            for (int k = 0; k < 4; k++)
                mma_f16_ss(tmem, ad + k * 2, bd + k * 2, MMA_IDESC, (kc > 0) || (k > 0));
            TC_COMMIT(sb + (buf ? SM_MBAR1 : SM_MBAR0));
        }
    }
    MBAR_WAIT(sb + SM_MBAR0, ph0);
    MBAR_WAIT(sb + SM_MBAR1, ph1);
    TC_FENCE_AFTER();
    __syncthreads();

    // stage col-block L/P/ne
    {
        float4* Lc4 = reinterpret_cast<float4*>(smem + SM_LC);
        float4* Pc4 = reinterpret_cast<float4*>(smem + SM_PC);
        const float4* GL4 = reinterpret_cast<const float4*>(g_L) + tj * TILE * 4;
        const float4* GP4 = reinterpret_cast<const float4*>(g_P) + tj * TILE * 4;
        for (int s = tid; s < 512; s += 256) { Lc4[s] = GL4[s]; Pc4[s] = GP4[s]; }
        float* nc = reinterpret_cast<float*>(smem + SM_NC);
        if (tid < 128) nc[tid] = g_ne[tj * TILE + tid];
    }
    __syncthreads();

    if (tid < 128) {
        float* Lc = reinterpret_cast<float*>(smem + SM_LC);
        float* Pc = reinterpret_cast<float*>(smem + SM_PC);
        float* nc = reinterpret_cast<float*>(smem + SM_NC);
        int gi = ti * TILE + tid;
        float Li[EDIM], Pi[EDIM];
        #pragma unroll
        for (int q = 0; q < 4; q++) {
            float4 a = reinterpret_cast<const float4*>(g_L + gi * EDIM)[q];
            float4 b = reinterpret_cast<const float4*>(g_P + gi * EDIM)[q];
            Li[q*4+0] = a.x; Li[q*4+1] = a.y; Li[q*4+2] = a.z; Li[q*4+3] = a.w;
            Pi[q*4+0] = b.x; Pi[q*4+1] = b.y; Pi[q*4+2] = b.z; Pi[q*4+3] = b.w;
        }
        float nei = g_ne[gi];
        #pragma unroll
        for (int cb = 0; cb < 4; cb++) {
            uint32_t d[32];
            LDTM_X32(d, tmem + cb * 32);
            TC_WAIT_LD();
            #pragma unroll
            for (int c = 0; c < 32; c++) {
                float s = __uint_as_float(d[c]);
                int jl = cb * 32 + c;
                if (s > SIM_THR && (!diag || jl != tid)) {
                    float d1 = 0.f;
                    #pragma unroll
                    for (int e = 0; e < EDIM; e++) d1 = fmaf(Li[e], Pc[jl * EDIM + e], d1);
                    float klij = nc[jl] - d1;
                    if (diag) { sumv += klij; cntv += 1u; }
                    else {
                        float d2 = 0.f;
                        #pragma unroll
                        for (int e = 0; e < EDIM; e++) d2 = fmaf(Lc[jl * EDIM + e], Pi[e], d2);
                        sumv += klij + (nei - d2);
                        cntv += 2u;
                    }
                }
            }
        }
        TC_FENCE_BEFORE();
    }
    __syncthreads();
    if (tid == 0) { MBAR_INVAL(sb + SM_MBAR0); MBAR_INVAL(sb + SM_MBAR1); }
    __syncthreads();
    if (wid == 0) TC_DEALLOC(tmem, 128);

#else
    // ======== Path B: mma.sync m16n8k16 bf16 ========
    // 8 warps: warp_m = wid>>2 (0..1), warp_n = wid&3 (0..3); warp tile 64x32.
    // SMEM stage: A/B 128 rows x 32 bf16, padded row stride 40 bf16 (80 B).
    const int wm = wid >> 2, wn = wid & 3;
    const int NSTAGE = HDIM / 32;    // 32
    // byte offsets: stage buf: A at 1024 + buf*20480, B at +10240
    float acc[4][4][4];
    #pragma unroll
    for (int f = 0; f < 4; f++)
        #pragma unroll
        for (int g = 0; g < 4; g++)
            #pragma unroll
            for (int r = 0; r < 4; r++) acc[f][g][r] = 0.f;

    const __nv_bfloat16* Abase = g_embn + (size_t)(ti * TILE) * HDIM;
    const __nv_bfloat16* Bbase = g_embn + (size_t)(tj * TILE) * HDIM;

    // per-thread copy mapping: idx = tid + q*256 (q=0,1); row = idx>>2; c16 = idx&3
    int cp_row0 = tid >> 2, cp_c0 = tid & 3;
    int cp_row1 = (tid + 256) >> 2, cp_c1 = (tid + 256) & 3;

    #define CPASYNC16(sa, gp) \
        asm volatile("cp.async.cg.shared.global [%0], [%1], 16;" :: "r"(sa), "l"(gp) : "memory")
    #define CP_COMMIT() asm volatile("cp.async.commit_group;" ::: "memory")

    #define COPY_STAGE(buf, st) do {                                              \
        uint32_t sA = sb + 1024 + (buf) * 20480;                                  \
        uint32_t sB = sA + 10240;                                                 \
        int k0 = (st) * 32;                                                       \
        CPASYNC16(sA + cp_row0 * 80 + cp_c0 * 16, Abase + (size_t)cp_row0 * HDIM + k0 + cp_c0 * 8); \
        CPASYNC16(sA + cp_row1 * 80 + cp_c1 * 16, Abase + (size_t)cp_row1 * HDIM + k0 + cp_c1 * 8); \
        CPASYNC16(sB + cp_row0 * 80 + cp_c0 * 16, Bbase + (size_t)cp_row0 * HDIM + k0 + cp_c0 * 8); \
        CPASYNC16(sB + cp_row1 * 80 + cp_c1 * 16, Bbase + (size_t)cp_row1 * HDIM + k0 + cp_c1 * 8); \
    } while (0)

    COPY_STAGE(0, 0);
    CP_COMMIT();

    for (int s = 0; s < NSTAGE; s++) {
        int buf = s & 1;
        if (s + 1 < NSTAGE) {
            COPY_STAGE(buf ^ 1, s + 1);
            CP_COMMIT();
            asm volatile("cp.async.wait_group 1;" ::: "memory");
        } else {
            asm volatile("cp.async.wait_group 0;" ::: "memory");
        }
        __syncthreads();

        uint32_t sA = sb + 1024 + buf * 20480;
        uint32_t sB = sA + 10240;
        #pragma unroll
        for (int kk = 0; kk < 2; kk++) {
            uint32_t a[4][4], b[4][2];
            #pragma unroll
            for (int f = 0; f < 4; f++) {
                uint32_t addr = sA + (uint32_t)(wm * 64 + f * 16 + (lane & 15)) * 80
                                + kk * 32 + (lane >> 4) * 16;
                asm volatile("ldmatrix.sync.aligned.m8n8.x4.shared.b16 {%0,%1,%2,%3}, [%4];"
                    : "=r"(a[f][0]), "=r"(a[f][1]), "=r"(a[f][2]), "=r"(a[f][3]) : "r"(addr));
            }
            #pragma unroll
            for (int g = 0; g < 4; g++) {
                uint32_t addr = sB + (uint32_t)(wn * 32 + g * 8 + (lane & 7)) * 80
                                + kk * 32 + ((lane >> 3) & 1) * 16;
                asm volatile("ldmatrix.sync.aligned.m8n8.x2.shared.b16 {%0,%1}, [%2];"
                    : "=r"(b[g][0]), "=r"(b[g][1]) : "r"(addr));
            }
            #pragma unroll
            for (int f = 0; f < 4; f++)
                #pragma unroll
                for (int g = 0; g < 4; g++)
                    asm volatile(
                        "mma.sync.aligned.m16n8k16.row.col.f32.bf16.bf16.f32 "
                        "{%0,%1,%2,%3}, {%4,%5,%6,%7}, {%8,%9}, {%0,%1,%2,%3};"
                        : "+f"(acc[f][g][0]), "+f"(acc[f][g][1]),
                          "+f"(acc[f][g][2]), "+f"(acc[f][g][3])
                        : "r"(a[f][0]), "r"(a[f][1]), "r"(a[f][2]), "r"(a[f][3]),
                          "r"(b[g][0]), "r"(b[g][1]));
        }
        __syncthreads();
    }

    // stage L/P/ne for row block and col block
    {
        float4* Lr4 = reinterpret_cast<float4*>(smem + 1024);
        float4* Pr4 = reinterpret_cast<float4*>(smem + 1024 + 8192);
        float4* Lc4 = reinterpret_cast<float4*>(smem + 1024 + 16384);
        float4* Pc4 = reinterpret_cast<float4*>(smem + 1024 + 24576);
        const float4* GLr = reinterpret_cast<const float4*>(g_L) + ti * TILE * 4;
        const float4* GPr = reinterpret_cast<const float4*>(g_P) + ti * TILE * 4;
        const float4* GLc = reinterpret_cast<const float4*>(g_L) + tj * TILE * 4;
        const float4* GPc = reinterpret_cast<const float4*>(g_P) + tj * TILE * 4;
        for (int s = tid; s < 512; s += 256) {
            Lr4[s] = GLr[s]; Pr4[s] = GPr[s]; Lc4[s] = GLc[s]; Pc4[s] = GPc[s];
        }
        float* nr = reinterpret_cast<float*>(smem + 1024 + 32768);
        float* nc = nr + 128;
        if (tid < 128) { nr[tid] = g_ne[ti * TILE + tid]; nc[tid] = g_ne[tj * TILE + tid]; }
    }
    __syncthreads();

    {
        float* Lr = reinterpret_cast<float*>(smem + 1024);
        float* Pr = reinterpret_cast<float*>(smem + 1024 + 8192);
        float* Lc = reinterpret_cast<float*>(smem + 1024 + 16384);
        float* Pc = reinterpret_cast<float*>(smem + 1024 + 24576);
        float* nr = reinterpret_cast<float*>(smem + 1024 + 32768);
        float* nc = nr + 128;
        int t4 = lane >> 2, t2 = (lane & 3) * 2;
        #pragma unroll
        for (int f = 0; f < 4; f++)
            #pragma unroll
            for (int g = 0; g < 4; g++)
                #pragma unroll
                for (int r = 0; r < 4; r++) {
                    float s = acc[f][g][r];
                    int i = wm * 64 + f * 16 + t4 + (r >> 1) * 8;
                    int j = wn * 32 + g * 8 + t2 + (r & 1);
                    if (s > SIM_THR && (!diag || i != j)) {
                        float d1 = 0.f;
                        #pragma unroll
                        for (int e = 0; e < EDIM; e++)
                            d1 = fmaf(Lr[i * 16 + e], Pc[j * 16 + e], d1);
                        float klij = nc[j] - d1;
                        if (diag) { sumv += klij; cntv += 1u; }
                        else {
                            float d2 = 0.f;
                            #pragma unroll
                            for (int e = 0; e < EDIM; e++)
                                d2 = fmaf(Lc[j * 16 + e], Pr[i * 16 + e], d2);
                            sumv += klij + (nr[i] - d2);
                            cntv += 2u;
                        }
                    }
                }
    }
#endif

    // block reduce + single atomic
    #pragma unroll
    for (int o = 16; o > 0; o >>= 1) {
        sumv += __shfl_down_sync(0xffffffffu, sumv, o);
        cntv += __shfl_down_sync(0xffffffffu, cntv, o);
    }
    float* rs = reinterpret_cast<float*>(smem + 64);
    unsigned int* rc = reinterpret_cast<unsigned int*>(smem + 96);
    if (lane == 0) { rs[wid] = sumv; rc[wid] = cntv; }
    __syncthreads();
    if (tid == 0) {
        float ts = 0.f; unsigned int tc = 0;
        #pragma unroll
        for (int q = 0; q < 8; q++) { ts += rs[q]; tc += rc[q]; }
        if (tc > 0) {
            atomicAdd(&g_sum, (double)ts);
            atomicAdd(&g_cnt, (unsigned long long)tc);
        }
    }
}

__global__ void finalize_kernel(float* __restrict__ out) {
    unsigned long long c = g_cnt;
    out[0] = (c > 0) ? (float)(g_sum / (double)c) : 0.0f;   // WEIGHT = 1.0
}

extern "C" void kernel_launch(void* const* d_in, const int* in_sizes, int n_in,
                              void* d_out, int out_size) {
    const float* rp;
    const float* emb;
    if (in_sizes[0] == BDIM * EDIM) {
        rp = (const float*)d_in[0];
        emb = (const float*)d_in[1];
    } else {
        rp = (const float*)d_in[1];
        emb = (const float*)d_in[0];
    }
    float* out = (float*)d_out;

    cudaFuncSetAttribute(main_kernel,
                         cudaFuncAttributeMaxDynamicSharedMemorySize, SM_TOTAL);

    init_kernel<<<1, 1>>>();
    normalize_kernel<<<BDIM, 256>>>(emb);
    routing_kernel<<<BDIM / 256, 256>>>(rp);
    main_kernel<<<NBLK, 256, SM_TOTAL>>>();
    finalize_kernel<<<1, 1>>>(out);
}

// round 4
// speedup vs baseline: 3.6148x; 1.0793x over previous
#include <cuda_runtime.h>
#include <cuda_bf16.h>
#include <cstdint>

// ConsistencyLoss: B=8192, E=16, H=1024
// Round 4: mma.sync bf16 (family-target safe) 256x128 supertile Gram GEMM
// with 3-stage cp.async pipeline and fused masked-KL epilogue.
// (tcgen05 removed: the build's PTX pass targets sm_103 family, which lacks
//  tcgen05.ld — TMEM accumulators are unreadable there.)

#define BDIM 8192
#define HDIM 1024
#define EDIM 16
#define SIM_THR 0.8f

// Supertile: A = 256 rows, B = 128 cols. Tiles (I,J): I in [0,32), J in [2I,64).
#define NTI 32
#define NTJ 64
#define NSBLK 1056            // sum_{I}(64-2I)

#define KSTAGE 64             // bf16 K-cols per stage (128 B per row)
#define NSTAGE (HDIM / KSTAGE)  // 16

// ---- dynamic SMEM layout (bytes) ----
#define SM_CTRL   1024
#define STAGE_B   49152       // A: 256*128 = 32768, B: 128*128 = 16384
#define SM_TOTAL  (SM_CTRL + 3 * STAGE_B)   // 148480
// epilogue staging (reuses stage region):
#define SM_LR 1024            // 256*16 f32 = 16384
#define SM_PR (SM_LR + 16384)
#define SM_LC (SM_PR + 16384) // 128*16 f32 = 8192
#define SM_PC (SM_LC + 8192)
#define SM_NR (SM_PC + 8192)  // 256 f32
#define SM_NC (SM_NR + 1024)  // 128 f32

__device__ __nv_bfloat16 g_embn[BDIM * HDIM];   // normalized embeddings (16 MB)
__device__ float  g_L[BDIM * EDIM];
__device__ float  g_P[BDIM * EDIM];
__device__ float  g_ne[BDIM];
__device__ double g_sum;
__device__ unsigned long long g_cnt;

__device__ __forceinline__ uint32_t smem_u32(const void* p) {
    uint32_t a;
    asm("{ .reg .u64 t; cvta.to.shared.u64 t, %1; cvt.u32.u64 %0, t; }" : "=r"(a) : "l"(p));
    return a;
}

#define CPASYNC16(sa, gp) \
    asm volatile("cp.async.cg.shared.global [%0], [%1], 16;" :: "r"(sa), "l"(gp) : "memory")
#define CP_COMMIT() asm volatile("cp.async.commit_group;" ::: "memory")
#define CP_WAIT2() asm volatile("cp.async.wait_group 2;" ::: "memory")
#define CP_WAIT0() asm volatile("cp.async.wait_group 0;" ::: "memory")

// ---------------- prep kernels ----------------
__global__ void init_kernel() { g_sum = 0.0; g_cnt = 0ull; }

__global__ void normalize_kernel(const float* __restrict__ emb) {
    int row = blockIdx.x;
    int t = threadIdx.x;
    float4 v = reinterpret_cast<const float4*>(emb + (size_t)row * HDIM)[t];
    float ss = v.x * v.x + v.y * v.y + v.z * v.z + v.w * v.w;
    #pragma unroll
    for (int o = 16; o > 0; o >>= 1) ss += __shfl_down_sync(0xffffffffu, ss, o);
    __shared__ float red[8];
    int lane = t & 31, w = t >> 5;
    if (lane == 0) red[w] = ss;
    __syncthreads();
    if (t < 32) {
        float s = (t < 8) ? red[t] : 0.f;
        #pragma unroll
        for (int o = 4; o > 0; o >>= 1) s += __shfl_down_sync(0xffffffffu, s, o);
        if (t == 0) red[0] = s;
    }
    __syncthreads();
    float inv = rsqrtf(red[0]);
    __nv_bfloat162 h0 = __floats2bfloat162_rn(v.x * inv, v.y * inv);
    __nv_bfloat162 h1 = __floats2bfloat162_rn(v.z * inv, v.w * inv);
    uint2 o2;
    *reinterpret_cast<__nv_bfloat162*>(&o2.x) = h0;
    *reinterpret_cast<__nv_bfloat162*>(&o2.y) = h1;
    reinterpret_cast<uint2*>(g_embn + (size_t)row * HDIM)[t] = o2;
}

__global__ void routing_kernel(const float* __restrict__ rp) {
    int row = blockIdx.x * blockDim.x + threadIdx.x;
    if (row >= BDIM) return;
    float x[EDIM];
    float m = -1e30f;
    #pragma unroll
    for (int e = 0; e < EDIM; e++) { x[e] = rp[row * EDIM + e]; m = fmaxf(m, x[e]); }
    float s = 0.f;
    #pragma unroll
    for (int e = 0; e < EDIM; e++) s += expf(x[e] - m);
    float lse = m + logf(s);
    float ne = 0.f;
    #pragma unroll
    for (int e = 0; e < EDIM; e++) {
        float L = x[e] - lse;
        float P = expf(L);
        g_L[row * EDIM + e] = L;
        g_P[row * EDIM + e] = P;
        ne = fmaf(P, L, ne);
    }
    g_ne[row] = ne;
}

// ---------------- main fused kernel ----------------
// 256 threads = 8 warps. Warp (wm = wid>>2 in {0,1}, wn = wid&3 in {0..3}).
// Per A-half h (0: rows 0-127, 1: rows 128-255): warp computes 64x32 tile
// at rows h*128 + wm*64 + [0,64), cols wn*32 + [0,32).
__global__ __launch_bounds__(256, 1) void main_kernel() {
    extern __shared__ char smem[];
    uint32_t sb = smem_u32(smem);
    int tid = threadIdx.x;
    int wid = tid >> 5, lane = tid & 31;
    const int wm = wid >> 2, wn = wid & 3;

    // block -> (I, J): J in [2I, 64)
    int I = 0, rem = blockIdx.x;
    while (rem >= NTJ - 2 * I) { rem -= NTJ - 2 * I; I++; }
    int J = 2 * I + rem;

    float acc[2][4][4][4];
    #pragma unroll
    for (int h = 0; h < 2; h++)
        #pragma unroll
        for (int f = 0; f < 4; f++)
            #pragma unroll
            for (int g = 0; g < 4; g++)
                #pragma unroll
                for (int r = 0; r < 4; r++) acc[h][f][g][r] = 0.f;

    const __nv_bfloat16* Abase = g_embn + (size_t)(I * 256 + tid) * HDIM;
    const int brow = tid >> 1;
    const int bq0 = (tid & 1) * 4;
    const __nv_bfloat16* Bbase = g_embn + (size_t)(J * 128 + brow) * HDIM;

    // copy stage s into ring buffer buf (each thread: 8 A-chunks + 4 B-chunks)
    #define COPY_STAGE(buf, s) do {                                               \
        uint32_t sA = sb + SM_CTRL + (buf) * STAGE_B;                             \
        uint32_t sB = sA + 32768;                                                 \
        int k0 = (s) * KSTAGE;                                                    \
        _Pragma("unroll")                                                         \
        for (int q = 0; q < 8; q++)                                               \
            CPASYNC16(sA + tid * 128 + ((q ^ (tid & 7)) * 16), Abase + k0 + q * 8); \
        _Pragma("unroll")                                                         \
        for (int q = 0; q < 4; q++) {                                             \
            int qq = bq0 + q;                                                     \
            CPASYNC16(sB + brow * 128 + ((qq ^ (brow & 7)) * 16), Bbase + k0 + qq * 8); \
        }                                                                         \
    } while (0)

    COPY_STAGE(0, 0); CP_COMMIT();
    COPY_STAGE(1, 1); CP_COMMIT();
    COPY_STAGE(2, 2); CP_COMMIT();

    for (int s = 0; s < NSTAGE; s++) {
        int buf = s - (s / 3) * 3;     // s % 3
        CP_WAIT2();
        __syncthreads();

        uint32_t sA = sb + SM_CTRL + buf * STAGE_B;
        uint32_t sB = sA + 32768;

        #pragma unroll
        for (int kk = 0; kk < 4; kk++) {
            // B fragments: reused by both A-halves
            uint32_t bf[4][2];
            #pragma unroll
            for (int g = 0; g < 4; g++) {
                int row = wn * 32 + g * 8 + (lane & 7);
                int ch = (kk * 2 + ((lane >> 3) & 1)) ^ (row & 7);
                uint32_t addr = sB + (uint32_t)row * 128 + ch * 16;
                asm volatile("ldmatrix.sync.aligned.m8n8.x2.shared.b16 {%0,%1}, [%2];"
                    : "=r"(bf[g][0]), "=r"(bf[g][1]) : "r"(addr));
            }
            #pragma unroll
            for (int f = 0; f < 4; f++) {
                int arow = wm * 64 + f * 16 + (lane & 15);
                int ach = (kk * 2 + (lane >> 4));
                uint32_t a0[4], a1[4];
                {
                    uint32_t addr = sA + (uint32_t)arow * 128 + ((ach ^ (arow & 7)) * 16);
                    asm volatile("ldmatrix.sync.aligned.m8n8.x4.shared.b16 {%0,%1,%2,%3}, [%4];"
                        : "=r"(a0[0]), "=r"(a0[1]), "=r"(a0[2]), "=r"(a0[3]) : "r"(addr));
                }
                {
                    int arow1 = arow + 128;
                    uint32_t addr = sA + (uint32_t)arow1 * 128 + ((ach ^ (arow1 & 7)) * 16);
                    asm volatile("ldmatrix.sync.aligned.m8n8.x4.shared.b16 {%0,%1,%2,%3}, [%4];"
                        : "=r"(a1[0]), "=r"(a1[1]), "=r"(a1[2]), "=r"(a1[3]) : "r"(addr));
                }
                #pragma unroll
                for (int g = 0; g < 4; g++) {
                    asm volatile(
                        "mma.sync.aligned.m16n8k16.row.col.f32.bf16.bf16.f32 "
                        "{%0,%1,%2,%3}, {%4,%5,%6,%7}, {%8,%9}, {%0,%1,%2,%3};"
                        : "+f"(acc[0][f][g][0]), "+f"(acc[0][f][g][1]),
                          "+f"(acc[0][f][g][2]), "+f"(acc[0][f][g][3])
                        : "r"(a0[0]), "r"(a0[1]), "r"(a0[2]), "r"(a0[3]),
                          "r"(bf[g][0]), "r"(bf[g][1]));
                    asm volatile(
                        "mma.sync.aligned.m16n8k16.row.col.f32.bf16.bf16.f32 "
                        "{%0,%1,%2,%3}, {%4,%5,%6,%7}, {%8,%9}, {%0,%1,%2,%3};"
                        : "+f"(acc[1][f][g][0]), "+f"(acc[1][f][g][1]),
                          "+f"(acc[1][f][g][2]), "+f"(acc[1][f][g][3])
                        : "r"(a1[0]), "r"(a1[1]), "r"(a1[2]), "r"(a1[3]),
                          "r"(bf[g][0]), "r"(bf[g][1]));
                }
            }
        }
        __syncthreads();
        if (s + 3 < NSTAGE) { COPY_STAGE(buf, s + 3); }
        CP_COMMIT();
    }
    CP_WAIT0();
    __syncthreads();

    // ---- stage L/P/ne: 256 A-rows and 128 B-cols (reuses stage region) ----
    {
        float4* Lr4 = reinterpret_cast<float4*>(smem + SM_LR);
        float4* Pr4 = reinterpret_cast<float4*>(smem + SM_PR);
        float4* Lc4 = reinterpret_cast<float4*>(smem + SM_LC);
        float4* Pc4 = reinterpret_cast<float4*>(smem + SM_PC);
        const float4* GLr = reinterpret_cast<const float4*>(g_L) + (size_t)I * 256 * 4;
        const float4* GPr = reinterpret_cast<const float4*>(g_P) + (size_t)I * 256 * 4;
        const float4* GLc = reinterpret_cast<const float4*>(g_L) + (size_t)J * 128 * 4;
        const float4* GPc = reinterpret_cast<const float4*>(g_P) + (size_t)J * 128 * 4;
        #pragma unroll
        for (int k = 0; k < 4; k++) {
            int s4 = tid + k * 256;     // 1024 float4 for 256 rows
            Lr4[s4] = GLr[s4];
            Pr4[s4] = GPr[s4];
        }
        #pragma unroll
        for (int k = 0; k < 2; k++) {
            int s4 = tid + k * 256;     // 512 float4 for 128 cols
            Lc4[s4] = GLc[s4];
            Pc4[s4] = GPc[s4];
        }
        float* nr = reinterpret_cast<float*>(smem + SM_NR);
        float* nc = reinterpret_cast<float*>(smem + SM_NC);
        nr[tid] = g_ne[I * 256 + tid];
        if (tid < 128) nc[tid] = g_ne[J * 128 + tid];
    }
    __syncthreads();

    float sumv = 0.f;
    unsigned int cntv = 0;
    {
        const float* Lr = reinterpret_cast<const float*>(smem + SM_LR);
        const float* Pr = reinterpret_cast<const float*>(smem + SM_PR);
        const float* Lc = reinterpret_cast<const float*>(smem + SM_LC);
        const float* Pc = reinterpret_cast<const float*>(smem + SM_PC);
        const float* nr = reinterpret_cast<const float*>(smem + SM_NR);
        const float* nc = reinterpret_cast<const float*>(smem + SM_NC);
        int t4 = lane >> 2, t2 = (lane & 3) * 2;
        #pragma unroll
        for (int h = 0; h < 2; h++) {
            int rel = J - (2 * I + h);
            if (rel < 0) continue;          // lower-triangular sub-block: skip
            bool diag = (rel == 0);
            #pragma unroll
            for (int f = 0; f < 4; f++)
                #pragma unroll
                for (int g = 0; g < 4; g++)
                    #pragma unroll
                    for (int r = 0; r < 4; r++) {
                        float s = acc[h][f][g][r];
                        int il = h * 128 + wm * 64 + f * 16 + t4 + (r >> 1) * 8;
                        int jl = wn * 32 + g * 8 + t2 + (r & 1);
                        if (s > SIM_THR && (!diag || (il & 127) != jl)) {
                            // kl[i,j] = ne_j - dot(L_i, P_j)
                            float d1 = 0.f;
                            #pragma unroll
                            for (int e = 0; e < EDIM; e++)
                                d1 = fmaf(Lr[il * 16 + e], Pc[jl * 16 + e], d1);
                            float klij = nc[jl] - d1;
                            if (diag) { sumv += klij; cntv += 1u; }
                            else {
                                // kl[j,i] = ne_i - dot(L_j, P_i)
                                float d2 = 0.f;
                                #pragma unroll
                                for (int e = 0; e < EDIM; e++)
                                    d2 = fmaf(Lc[jl * 16 + e], Pr[il * 16 + e], d2);
                                sumv += klij + (nr[il] - d2);
                                cntv += 2u;
                            }
                        }
                    }
        }
    }

    // block reduce + single atomic
    #pragma unroll
    for (int o = 16; o > 0; o >>= 1) {
        sumv += __shfl_down_sync(0xffffffffu, sumv, o);
        cntv += __shfl_down_sync(0xffffffffu, cntv, o);
    }
    float* rs = reinterpret_cast<float*>(smem + 64);
    unsigned int* rc = reinterpret_cast<unsigned int*>(smem + 96);
    if (lane == 0) { rs[wid] = sumv; rc[wid] = cntv; }
    __syncthreads();
    if (tid == 0) {
        float ts = 0.f; unsigned int tc = 0;
        #pragma unroll
        for (int q = 0; q < 8; q++) { ts += rs[q]; tc += rc[q]; }
        if (tc > 0) {
            atomicAdd(&g_sum, (double)ts);
            atomicAdd(&g_cnt, (unsigned long long)tc);
        }
    }
}

__global__ void finalize_kernel(float* __restrict__ out) {
    unsigned long long c = g_cnt;
    out[0] = (c > 0) ? (float)(g_sum / (double)c) : 0.0f;   // WEIGHT = 1.0
}

extern "C" void kernel_launch(void* const* d_in, const int* in_sizes, int n_in,
                              void* d_out, int out_size) {
    const float* rp;
    const float* emb;
    if (in_sizes[0] == BDIM * EDIM) {
        rp = (const float*)d_in[0];
        emb = (const float*)d_in[1];
    } else {
        rp = (const float*)d_in[1];
        emb = (const float*)d_in[0];
    }
    float* out = (float*)d_out;

    cudaFuncSetAttribute(main_kernel,
                         cudaFuncAttributeMaxDynamicSharedMemorySize, SM_TOTAL);

    init_kernel<<<1, 1>>>();
    normalize_kernel<<<BDIM, 256>>>(emb);
    routing_kernel<<<BDIM / 256, 256>>>(rp);
    main_kernel<<<NSBLK, 256, SM_TOTAL>>>();
    finalize_kernel<<<1, 1>>>(out);
}

// round 5
// speedup vs baseline: 5.8311x; 1.6131x over previous
#include <cuda_runtime.h>
#include <cuda_bf16.h>
#include <cstdint>

// ConsistencyLoss: B=8192, E=16, H=1024
// Round 5: mma.sync bf16 128x128 Gram tiles, 3-stage cp.async, tuned for
// 2 CTAs/SM (occupancy was the round-4 bottleneck), fused masked-KL epilogue.

#define BDIM 8192
#define HDIM 1024
#define EDIM 16
#define TILE 128
#define NT   (BDIM / TILE)            // 64
#define NBLK (NT * (NT + 1) / 2)      // 2080
#define SIM_THR 0.8f

#define KSTAGE 64                     // bf16 K-cols per stage (128 B/row)
#define NSTAGE (HDIM / KSTAGE)        // 16

// ---- dynamic SMEM layout (bytes) ----
#define SM_CTRL   1024
#define STAGE_B   32768               // A: 128*128B = 16K, B: 16K
#define SM_TOTAL  (SM_CTRL + 3 * STAGE_B)   // 99328  (2 CTAs -> 194.5 KB/SM)
// epilogue staging (reuses stage region):
#define SM_LR 1024                    // 128*16 f32 = 8192
#define SM_PR (SM_LR + 8192)
#define SM_LC (SM_PR + 8192)
#define SM_PC (SM_LC + 8192)
#define SM_NR (SM_PC + 8192)          // 128 f32
#define SM_NC (SM_NR + 512)

__device__ __nv_bfloat16 g_embn[BDIM * HDIM];   // normalized embeddings (16 MB)
__device__ float  g_L[BDIM * EDIM];
__device__ float  g_P[BDIM * EDIM];
__device__ float  g_ne[BDIM];
__device__ double g_sum;
__device__ unsigned long long g_cnt;

__device__ __forceinline__ uint32_t smem_u32(const void* p) {
    uint32_t a;
    asm("{ .reg .u64 t; cvta.to.shared.u64 t, %1; cvt.u32.u64 %0, t; }" : "=r"(a) : "l"(p));
    return a;
}

#define CPASYNC16(sa, gp) \
    asm volatile("cp.async.cg.shared.global [%0], [%1], 16;" :: "r"(sa), "l"(gp) : "memory")
#define CP_COMMIT() asm volatile("cp.async.commit_group;" ::: "memory")
#define CP_WAIT2() asm volatile("cp.async.wait_group 2;" ::: "memory")
#define CP_WAIT0() asm volatile("cp.async.wait_group 0;" ::: "memory")

// ---------------- prep kernels ----------------
__global__ void init_kernel() { g_sum = 0.0; g_cnt = 0ull; }

__global__ void normalize_kernel(const float* __restrict__ emb) {
    int row = blockIdx.x;
    int t = threadIdx.x;
    float4 v = reinterpret_cast<const float4*>(emb + (size_t)row * HDIM)[t];
    float ss = v.x * v.x + v.y * v.y + v.z * v.z + v.w * v.w;
    #pragma unroll
    for (int o = 16; o > 0; o >>= 1) ss += __shfl_down_sync(0xffffffffu, ss, o);
    __shared__ float red[8];
    int lane = t & 31, w = t >> 5;
    if (lane == 0) red[w] = ss;
    __syncthreads();
    if (t < 32) {
        float s = (t < 8) ? red[t] : 0.f;
        #pragma unroll
        for (int o = 4; o > 0; o >>= 1) s += __shfl_down_sync(0xffffffffu, s, o);
        if (t == 0) red[0] = s;
    }
    __syncthreads();
    float inv = rsqrtf(red[0]);
    __nv_bfloat162 h0 = __floats2bfloat162_rn(v.x * inv, v.y * inv);
    __nv_bfloat162 h1 = __floats2bfloat162_rn(v.z * inv, v.w * inv);
    uint2 o2;
    *reinterpret_cast<__nv_bfloat162*>(&o2.x) = h0;
    *reinterpret_cast<__nv_bfloat162*>(&o2.y) = h1;
    reinterpret_cast<uint2*>(g_embn + (size_t)row * HDIM)[t] = o2;
}

__global__ void routing_kernel(const float* __restrict__ rp) {
    int row = blockIdx.x * blockDim.x + threadIdx.x;
    if (row >= BDIM) return;
    float x[EDIM];
    float m = -1e30f;
    #pragma unroll
    for (int e = 0; e < EDIM; e++) { x[e] = rp[row * EDIM + e]; m = fmaxf(m, x[e]); }
    float s = 0.f;
    #pragma unroll
    for (int e = 0; e < EDIM; e++) s += expf(x[e] - m);
    float lse = m + logf(s);
    float ne = 0.f;
    #pragma unroll
    for (int e = 0; e < EDIM; e++) {
        float L = x[e] - lse;
        float P = expf(L);
        g_L[row * EDIM + e] = L;
        g_P[row * EDIM + e] = P;
        ne = fmaf(P, L, ne);
    }
    g_ne[row] = ne;
}

// ---------------- main fused kernel ----------------
// 256 threads = 8 warps, warp grid 2x4: wm in {0,1} (64 rows), wn in {0..3}
// (32 cols). Per-thread acc = 4x4x4 = 64 f32.
__global__ __launch_bounds__(256, 2) void main_kernel() {
    extern __shared__ char smem[];
    uint32_t sb = smem_u32(smem);
    int tid = threadIdx.x;
    int wid = tid >> 5, lane = tid & 31;
    const int wm = wid >> 2, wn = wid & 3;

    // block -> (ti, tj), tj >= ti
    int ti = 0, rem = blockIdx.x;
    while (rem >= NT - ti) { rem -= NT - ti; ti++; }
    int tj = ti + rem;
    bool diag = (ti == tj);

    float acc[4][4][4];
    #pragma unroll
    for (int f = 0; f < 4; f++)
        #pragma unroll
        for (int g = 0; g < 4; g++)
            #pragma unroll
            for (int r = 0; r < 4; r++) acc[f][g][r] = 0.f;

    // copy mapping: each thread handles half a row (4 x 16B chunks)
    const int crow = tid >> 1;
    const int cq0 = (tid & 1) * 4;
    const __nv_bfloat16* Abase = g_embn + (size_t)(ti * TILE + crow) * HDIM;
    const __nv_bfloat16* Bbase = g_embn + (size_t)(tj * TILE + crow) * HDIM;

    #define COPY_STAGE(buf, s) do {                                               \
        uint32_t sA = sb + SM_CTRL + (buf) * STAGE_B;                             \
        uint32_t sB = sA + 16384;                                                 \
        int k0 = (s) * KSTAGE;                                                    \
        _Pragma("unroll")                                                         \
        for (int q = 0; q < 4; q++) {                                             \
            int qq = cq0 + q;                                                     \
            uint32_t soff = crow * 128 + ((qq ^ (crow & 7)) * 16);                \
            CPASYNC16(sA + soff, Abase + k0 + qq * 8);                            \
            CPASYNC16(sB + soff, Bbase + k0 + qq * 8);                            \
        }                                                                         \
    } while (0)

    COPY_STAGE(0, 0); CP_COMMIT();
    COPY_STAGE(1, 1); CP_COMMIT();
    COPY_STAGE(2, 2); CP_COMMIT();

    for (int s = 0; s < NSTAGE; s++) {
        int buf = s - (s / 3) * 3;     // s % 3
        CP_WAIT2();
        __syncthreads();

        uint32_t sA = sb + SM_CTRL + buf * STAGE_B;
        uint32_t sB = sA + 16384;

        #pragma unroll
        for (int kk = 0; kk < 4; kk++) {
            uint32_t bf[4][2];
            #pragma unroll
            for (int g = 0; g < 4; g++) {
                int row = wn * 32 + g * 8 + (lane & 7);
                int ch = (kk * 2 + ((lane >> 3) & 1)) ^ (row & 7);
                uint32_t addr = sB + (uint32_t)row * 128 + ch * 16;
                asm volatile("ldmatrix.sync.aligned.m8n8.x2.shared.b16 {%0,%1}, [%2];"
                    : "=r"(bf[g][0]), "=r"(bf[g][1]) : "r"(addr));
            }
            #pragma unroll
            for (int f = 0; f < 4; f++) {
                int arow = wm * 64 + f * 16 + (lane & 15);
                int ach = (kk * 2 + (lane >> 4)) ^ (arow & 7);
                uint32_t a[4];
                uint32_t addr = sA + (uint32_t)arow * 128 + ach * 16;
                asm volatile("ldmatrix.sync.aligned.m8n8.x4.shared.b16 {%0,%1,%2,%3}, [%4];"
                    : "=r"(a[0]), "=r"(a[1]), "=r"(a[2]), "=r"(a[3]) : "r"(addr));
                #pragma unroll
                for (int g = 0; g < 4; g++)
                    asm volatile(
                        "mma.sync.aligned.m16n8k16.row.col.f32.bf16.bf16.f32 "
                        "{%0,%1,%2,%3}, {%4,%5,%6,%7}, {%8,%9}, {%0,%1,%2,%3};"
                        : "+f"(acc[f][g][0]), "+f"(acc[f][g][1]),
                          "+f"(acc[f][g][2]), "+f"(acc[f][g][3])
                        : "r"(a[0]), "r"(a[1]), "r"(a[2]), "r"(a[3]),
                          "r"(bf[g][0]), "r"(bf[g][1]));
            }
        }
        __syncthreads();
        if (s + 3 < NSTAGE) { COPY_STAGE(buf, s + 3); }
        CP_COMMIT();
    }
    CP_WAIT0();
    __syncthreads();

    // ---- stage L/P/ne for row block and col block ----
    {
        float4* Lr4 = reinterpret_cast<float4*>(smem + SM_LR);
        float4* Pr4 = reinterpret_cast<float4*>(smem + SM_PR);
        float4* Lc4 = reinterpret_cast<float4*>(smem + SM_LC);
        float4* Pc4 = reinterpret_cast<float4*>(smem + SM_PC);
        const float4* GLr = reinterpret_cast<const float4*>(g_L) + (size_t)ti * TILE * 4;
        const float4* GPr = reinterpret_cast<const float4*>(g_P) + (size_t)ti * TILE * 4;
        const float4* GLc = reinterpret_cast<const float4*>(g_L) + (size_t)tj * TILE * 4;
        const float4* GPc = reinterpret_cast<const float4*>(g_P) + (size_t)tj * TILE * 4;
        for (int s = tid; s < 512; s += 256) {
            Lr4[s] = GLr[s]; Pr4[s] = GPr[s]; Lc4[s] = GLc[s]; Pc4[s] = GPc[s];
        }
        float* nr = reinterpret_cast<float*>(smem + SM_NR);
        float* nc = reinterpret_cast<float*>(smem + SM_NC);
        if (tid < 128) { nr[tid] = g_ne[ti * TILE + tid]; nc[tid] = g_ne[tj * TILE + tid]; }
    }
    __syncthreads();

    float sumv = 0.f;
    unsigned int cntv = 0;
    {
        const float* Lr = reinterpret_cast<const float*>(smem + SM_LR);
        const float* Pr = reinterpret_cast<const float*>(smem + SM_PR);
        const float* Lc = reinterpret_cast<const float*>(smem + SM_LC);
        const float* Pc = reinterpret_cast<const float*>(smem + SM_PC);
        const float* nr = reinterpret_cast<const float*>(smem + SM_NR);
        const float* nc = reinterpret_cast<const float*>(smem + SM_NC);
        int t4 = lane >> 2, t2 = (lane & 3) * 2;
        #pragma unroll
        for (int f = 0; f < 4; f++)
            #pragma unroll
            for (int g = 0; g < 4; g++)
                #pragma unroll
                for (int r = 0; r < 4; r++) {
                    float s = acc[f][g][r];
                    int i = wm * 64 + f * 16 + t4 + (r >> 1) * 8;
                    int j = wn * 32 + g * 8 + t2 + (r & 1);
                    if (s > SIM_THR && (!diag || i != j)) {
                        float d1 = 0.f;
                        #pragma unroll
                        for (int e = 0; e < EDIM; e++)
                            d1 = fmaf(Lr[i * 16 + e], Pc[j * 16 + e], d1);
                        float klij = nc[j] - d1;
                        if (diag) { sumv += klij; cntv += 1u; }
                        else {
                            float d2 = 0.f;
                            #pragma unroll
                            for (int e = 0; e < EDIM; e++)
                                d2 = fmaf(Lc[j * 16 + e], Pr[i * 16 + e], d2);
                            sumv += klij + (nr[i] - d2);
                            cntv += 2u;
                        }
                    }
                }
    }

    // block reduce + single atomic
    #pragma unroll
    for (int o = 16; o > 0; o >>= 1) {
        sumv += __shfl_down_sync(0xffffffffu, sumv, o);
        cntv += __shfl_down_sync(0xffffffffu, cntv, o);
    }
    float* rs = reinterpret_cast<float*>(smem + 64);
    unsigned int* rc = reinterpret_cast<unsigned int*>(smem + 96);
    if (lane == 0) { rs[wid] = sumv; rc[wid] = cntv; }
    __syncthreads();
    if (tid == 0) {
        float ts = 0.f; unsigned int tc = 0;
        #pragma unroll
        for (int q = 0; q < 8; q++) { ts += rs[q]; tc += rc[q]; }
        if (tc > 0) {
            atomicAdd(&g_sum, (double)ts);
            atomicAdd(&g_cnt, (unsigned long long)tc);
        }
    }
}

__global__ void finalize_kernel(float* __restrict__ out) {
    unsigned long long c = g_cnt;
    out[0] = (c > 0) ? (float)(g_sum / (double)c) : 0.0f;   // WEIGHT = 1.0
}

extern "C" void kernel_launch(void* const* d_in, const int* in_sizes, int n_in,
                              void* d_out, int out_size) {
    const float* rp;
    const float* emb;
    if (in_sizes[0] == BDIM * EDIM) {
        rp = (const float*)d_in[0];
        emb = (const float*)d_in[1];
    } else {
        rp = (const float*)d_in[1];
        emb = (const float*)d_in[0];
    }
    float* out = (float*)d_out;

    cudaFuncSetAttribute(main_kernel,
                         cudaFuncAttributeMaxDynamicSharedMemorySize, SM_TOTAL);

    init_kernel<<<1, 1>>>();
    normalize_kernel<<<BDIM, 256>>>(emb);
    routing_kernel<<<BDIM / 256, 256>>>(rp);
    main_kernel<<<NBLK, 256, SM_TOTAL>>>();
    finalize_kernel<<<1, 1>>>(out);
}